// round 5
// baseline (speedup 1.0000x reference)
#include <cuda_runtime.h>
#include <cuda_bf16.h>

// SCINet on GB300 — round 5: fp32x2 packed-FMA conv-as-GEMM (audited resubmit).
// Inner loops use PTX fma.rn.f32x2 (Blackwell packed fp32, 2 FMA/issue) over
// co-pairs: w-pair is an adjacent float2 in smem (LDS.64), x is duplicated
// into both halves once per ci. Bit-exact vs scalar fmaf per lane.
// Tree recursion via strided addressing on two ping-pong (B,D,1024) buffers.

#define BN   32
#define DN   192
#define CHN  768
#define TN   1024
#define OUTL 512
#define LT   64

// ---------------- packed fp32 helpers ---------------------------------------
__device__ __forceinline__ unsigned long long pk2(float lo, float hi) {
    unsigned long long r;
    asm("mov.b64 %0, {%1, %2};" : "=l"(r) : "f"(lo), "f"(hi));
    return r;
}
__device__ __forceinline__ void upk2(float& lo, float& hi, unsigned long long v) {
    asm("mov.b64 {%0, %1}, %2;" : "=f"(lo), "=f"(hi) : "l"(v));
}
__device__ __forceinline__ void fma2(unsigned long long& d,
                                     unsigned long long a, unsigned long long b) {
    asm("fma.rn.f32x2 %0, %1, %2, %0;" : "+l"(d) : "l"(a), "l"(b));
}

// ---------------- static device scratch (no allocations allowed) ------------
__device__ float g_bufA[BN * DN * TN];            // 25.2 MB
__device__ float g_bufB[BN * DN * TN];            // 25.2 MB
__device__ float g_h  [2 * BN * CHN * 514];       // 101 MB (max hLen = 514)
__device__ float g_bro[2 * BN * DN * 512];        // 25.2 MB
__device__ float g_cd [2 * BN * DN * 512];        // 25.2 MB  (d then c)

// ---------------- transpose x (B,T,D) -> (B,D,T) ----------------------------
__global__ void transpose_kernel(const float* __restrict__ x, float* __restrict__ o) {
    __shared__ float tile[32][33];
    int b = blockIdx.z, t0 = blockIdx.x * 32, d0 = blockIdx.y * 32;
    int tx = threadIdx.x, ty = threadIdx.y;
    for (int i = ty; i < 32; i += 8)
        tile[i][tx] = x[((size_t)b * TN + t0 + i) * DN + d0 + tx];
    __syncthreads();
    for (int i = ty; i < 32; i += 8)
        o[((size_t)b * DN + d0 + i) * TN + t0 + tx] = tile[tx][i];
}

// R(B,D,T) = tree(B,D,T) + x(B,T,D)^T
__global__ void addres_kernel(const float* __restrict__ x, const float* __restrict__ tr,
                              float* __restrict__ R) {
    __shared__ float tile[32][33];
    int b = blockIdx.z, t0 = blockIdx.x * 32, d0 = blockIdx.y * 32;
    int tx = threadIdx.x, ty = threadIdx.y;
    for (int i = ty; i < 32; i += 8)
        tile[i][tx] = x[((size_t)b * TN + t0 + i) * DN + d0 + tx];
    __syncthreads();
    for (int i = ty; i < 32; i += 8) {
        size_t oo = ((size_t)b * DN + d0 + i) * TN + t0 + tx;
        R[oo] = tile[tx][i] + tr[oo];
    }
}

// ---------------- conv1: Cin=192 -> Cout=768, k=5, replication pad, LeakyReLU
// h[(g*32+b)*768+co][l'], l' in [0, L+2): h[l'] = b + sum_k w[k]*x[clamp(l'+k-3)]
// Input element (b, ci, t): in[goff_g + (b*192+ci)*inRow + t*inStride]
__global__ void __launch_bounds__(256)
conv1_kernel(const float* __restrict__ in, int inRow, int inStride,
             long long goff0, long long goff1, int L,
             const float* __restrict__ W1, const float* __restrict__ b1,
             int wbase, float* __restrict__ h) {
    extern __shared__ float smem[];
    float* sx = smem;                     // [192][68] (LT+4 cols, pitch 68)
    float* sw = smem + DN * 68;           // [160][pitch 66], rest = ci*5+k, col co

    int z = blockIdx.z;                   // g*32+b
    int g = z >> 5, b = z & 31;
    int l0 = blockIdx.x * LT;
    int co0 = blockIdx.y * 64;
    int hLen = L + 2;
    int branch = wbase + g;
    long long goff = g ? goff1 : goff0;
    int tid = threadIdx.x;

    const float* inB = in + goff + (size_t)b * DN * inRow;

    // load x tile: 192 x 68, clamped time index (replication pad)
    for (int idx = tid; idx < DN * 68; idx += 256) {
        int ci = idx / 68;
        int col = idx - ci * 68;
        int t = l0 + col - 3;
        t = max(0, min(L - 1, t));
        sx[idx] = inB[(size_t)ci * inRow + (size_t)t * inStride];
    }

    int co_g = tid >> 3;   // 0..31 -> co pair
    int l_g  = tid & 7;    // 0..7  -> 8 l each
    const float* Wb = W1 + (size_t)branch * CHN * DN * 5;
    unsigned long long bias2 = pk2(b1[branch * CHN + co0 + co_g * 2 + 0],
                                   b1[branch * CHN + co0 + co_g * 2 + 1]);
    unsigned long long acc2[8];
#pragma unroll
    for (int i = 0; i < 8; i++) acc2[i] = bias2;

    for (int cc = 0; cc < DN; cc += 32) {
        __syncthreads();
        // weights: 64 co x (32 ci x 5 k); gmem coalesced along (ci,k)
        for (int idx = tid; idx < 64 * 160; idx += 256) {
            int co = idx / 160;
            int rest = idx - co * 160;            // ci*5+k
            sw[rest * 66 + co] = Wb[(size_t)(co0 + co) * (DN * 5) + (size_t)cc * 5 + rest];
        }
        __syncthreads();
        const float* sxc = sx + cc * 68 + l_g * 8;
        for (int ci = 0; ci < 32; ++ci) {
            const float* xp = sxc + ci * 68;
            float4 a0 = *(const float4*)(xp);
            float4 a1 = *(const float4*)(xp + 4);
            float4 a2 = *(const float4*)(xp + 8);
            unsigned long long xd[12];
            xd[0]  = pk2(a0.x, a0.x); xd[1]  = pk2(a0.y, a0.y);
            xd[2]  = pk2(a0.z, a0.z); xd[3]  = pk2(a0.w, a0.w);
            xd[4]  = pk2(a1.x, a1.x); xd[5]  = pk2(a1.y, a1.y);
            xd[6]  = pk2(a1.z, a1.z); xd[7]  = pk2(a1.w, a1.w);
            xd[8]  = pk2(a2.x, a2.x); xd[9]  = pk2(a2.y, a2.y);
            xd[10] = pk2(a2.z, a2.z); xd[11] = pk2(a2.w, a2.w);
#pragma unroll
            for (int k = 0; k < 5; ++k) {
                // adjacent co pair: one 8B-aligned LDS.64
                unsigned long long w2 =
                    *(const unsigned long long*)&sw[(ci * 5 + k) * 66 + co_g * 2];
#pragma unroll
                for (int i = 0; i < 8; i++) fma2(acc2[i], w2, xd[i + k]);
            }
        }
    }

    {
        int co = co0 + co_g * 2;
        float* hp0 = h + ((size_t)z * CHN + co) * hLen;
        float* hp1 = hp0 + hLen;
#pragma unroll
        for (int i = 0; i < 8; i++) {
            int l = l0 + l_g * 8 + i;
            if (l < hLen) {
                float v0, v1;
                upk2(v0, v1, acc2[i]);
                hp0[l] = v0 > 0.f ? v0 : 0.01f * v0;
                hp1[l] = v1 > 0.f ? v1 : 0.01f * v1;
            }
        }
    }
}

// ---------------- conv2: Cin=768 -> Cout=192, k=3, valid, Tanh ---------------
__global__ void __launch_bounds__(256)
conv2_kernel(const float* __restrict__ h, int hLen, int L,
             const float* __restrict__ W2, const float* __restrict__ b2,
             int wbase, float* __restrict__ bro) {
    __shared__ float sh[32 * 68];     // 32 ch x (LT+2), pitch 68
    __shared__ float sw[96 * 66];     // rest = ch*3+k, col co, pitch 66

    int z = blockIdx.z;
    int g = z >> 5;
    int l0 = blockIdx.x * LT;
    int co0 = blockIdx.y * 64;
    int branch = wbase + g;
    int tid = threadIdx.x;

    const float* hB = h + (size_t)z * CHN * hLen;
    const float* Wb = W2 + (size_t)branch * DN * CHN * 3;

    int co_g = tid >> 3;
    int l_g  = tid & 7;
    unsigned long long bias2 = pk2(b2[branch * DN + co0 + co_g * 2 + 0],
                                   b2[branch * DN + co0 + co_g * 2 + 1]);
    unsigned long long acc2[8];
#pragma unroll
    for (int i = 0; i < 8; i++) acc2[i] = bias2;

    for (int chc = 0; chc < CHN; chc += 32) {
        __syncthreads();
        for (int idx = tid; idx < 32 * 68; idx += 256) {
            int r = idx / 68;
            int cpos = idx - r * 68;
            int l = min(l0 + cpos, hLen - 1);
            sh[idx] = hB[(size_t)(chc + r) * hLen + l];
        }
        for (int idx = tid; idx < 64 * 96; idx += 256) {
            int co = idx / 96;
            int rest = idx - co * 96;             // ch*3+k
            sw[rest * 66 + co] = Wb[(size_t)(co0 + co) * (CHN * 3) + (size_t)chc * 3 + rest];
        }
        __syncthreads();
        for (int ch = 0; ch < 32; ++ch) {
            const float* xp = &sh[ch * 68 + l_g * 8];
            float4 a0 = *(const float4*)(xp);
            float4 a1 = *(const float4*)(xp + 4);
            float2 a2 = *(const float2*)(xp + 8);
            unsigned long long xd[10];
            xd[0] = pk2(a0.x, a0.x); xd[1] = pk2(a0.y, a0.y);
            xd[2] = pk2(a0.z, a0.z); xd[3] = pk2(a0.w, a0.w);
            xd[4] = pk2(a1.x, a1.x); xd[5] = pk2(a1.y, a1.y);
            xd[6] = pk2(a1.z, a1.z); xd[7] = pk2(a1.w, a1.w);
            xd[8] = pk2(a2.x, a2.x); xd[9] = pk2(a2.y, a2.y);
#pragma unroll
            for (int k = 0; k < 3; ++k) {
                unsigned long long w2 =
                    *(const unsigned long long*)&sw[(ch * 3 + k) * 66 + co_g * 2];
#pragma unroll
                for (int i = 0; i < 8; i++) fma2(acc2[i], w2, xd[i + k]);
            }
        }
    }

    {
        int co = co0 + co_g * 2;
        float* op0 = bro + ((size_t)z * DN + co) * L;
        float* op1 = op0 + L;
#pragma unroll
        for (int i = 0; i < 8; i++) {
            int l = l0 + l_g * 8 + i;
            if (l < L) {
                float v0, v1;
                upk2(v0, v1, acc2[i]);
                op0[l] = tanhf(v0);
                op1[l] = tanhf(v1);
            }
        }
    }
}

// ---------------- pointwise -------------------------------------------------
// d = odd * exp(phi); c = even * exp(psi)
__global__ void pw1_kernel(const float* __restrict__ M, int mRow, int strideB,
                           long long off, long long sHalf, int L,
                           const float* __restrict__ bro, float* __restrict__ cd) {
    int i = blockIdx.x * 256 + threadIdx.x;
    int N = BN * DN * L;
    if (i >= N) return;
    int t = i % L;
    int bd = i / L;
    size_t pos = (size_t)bd * mRow + (size_t)t * strideB + off;
    float ev = M[pos];
    float od = M[pos + sHalf];
    size_t CL = (size_t)N;
    cd[i]      = od * expf(bro[i]);        // d = odd * exp(phi)
    cd[CL + i] = ev * expf(bro[CL + i]);   // c = even * exp(psi)
}

// even_out = c + eta; odd_out = d - rho; written strided into master out buffer
__global__ void pw2_kernel(const float* __restrict__ cd, int L,
                           const float* __restrict__ bro, float* __restrict__ M,
                           int mRow, int strideB, long long off, long long sHalf) {
    int i = blockIdx.x * 256 + threadIdx.x;
    int N = BN * DN * L;
    if (i >= N) return;
    int t = i % L;
    int bd = i / L;
    size_t CL = (size_t)N;
    float dv = cd[i];
    float cv = cd[CL + i];
    size_t pos = (size_t)bd * mRow + (size_t)t * strideB + off;
    M[pos]         = cv + bro[i];          // even_up = c + eta(d)
    M[pos + sHalf] = dv - bro[CL + i];     // odd_up  = d - rho(c)
}

// ---------------- projection: out[b,o,d] = sum_t R[b,d,t] * Wp[o,t] ---------
__global__ void __launch_bounds__(256)
proj_kernel(const float* __restrict__ R, const float* __restrict__ Wp,
            float* __restrict__ out) {
    __shared__ float sW[32 * 66];   // [t][o], pitch 66 (8B-aligned pairs)
    __shared__ float sR[32 * 68];   // [t][d], pitch 68 (16B-aligned quads)
    int d0 = blockIdx.x * 64;
    int o0 = blockIdx.y * 64;
    int b = blockIdx.z;
    int tid = threadIdx.x;
    int og = tid >> 3, dg = tid & 7;
    unsigned long long acc2[8];
#pragma unroll
    for (int i = 0; i < 8; i++) acc2[i] = 0ULL;
    for (int t0 = 0; t0 < TN; t0 += 32) {
        __syncthreads();
        for (int idx = tid; idx < 2048; idx += 256) {
            int t = idx & 31, o = idx >> 5;
            sW[t * 66 + o] = Wp[(size_t)(o0 + o) * TN + t0 + t];
        }
        for (int idx = tid; idx < 2048; idx += 256) {
            int t = idx & 31, d = idx >> 5;
            sR[t * 68 + d] = R[((size_t)b * DN + d0 + d) * TN + t0 + t];
        }
        __syncthreads();
        for (int t = 0; t < 32; t++) {
            const float* rp = &sR[t * 68 + dg * 8];
            float4 r0 = *(const float4*)(rp);
            float4 r1 = *(const float4*)(rp + 4);
            unsigned long long rd[8];
            rd[0] = pk2(r0.x, r0.x); rd[1] = pk2(r0.y, r0.y);
            rd[2] = pk2(r0.z, r0.z); rd[3] = pk2(r0.w, r0.w);
            rd[4] = pk2(r1.x, r1.x); rd[5] = pk2(r1.y, r1.y);
            rd[6] = pk2(r1.z, r1.z); rd[7] = pk2(r1.w, r1.w);
            unsigned long long w2 =
                *(const unsigned long long*)&sW[t * 66 + og * 2];
#pragma unroll
            for (int i = 0; i < 8; i++) fma2(acc2[i], w2, rd[i]);
        }
    }
    {
        int o = o0 + og * 2;
        float* out0 = out + ((size_t)b * OUTL + o) * DN + d0 + dg * 8;
        float* out1 = out0 + DN;
#pragma unroll
        for (int i = 0; i < 8; i++) {
            float v0, v1;
            upk2(v0, v1, acc2[i]);
            out0[i] = v0;
            out1[i] = v1;
        }
    }
}

// ---------------- host ------------------------------------------------------
extern "C" void kernel_launch(void* const* d_in, const int* in_sizes, int n_in,
                              void* d_out, int out_size) {
    const float* x  = (const float*)d_in[0];
    const float* W1 = (const float*)d_in[1];
    const float* b1 = (const float*)d_in[2];
    const float* W2 = (const float*)d_in[3];
    const float* b2 = (const float*)d_in[4];
    const float* Wp = (const float*)d_in[5];
    float* out = (float*)d_out;

    float *bufA, *bufB, *hb, *bro, *cd;
    cudaGetSymbolAddress((void**)&bufA, g_bufA);
    cudaGetSymbolAddress((void**)&bufB, g_bufB);
    cudaGetSymbolAddress((void**)&hb,   g_h);
    cudaGetSymbolAddress((void**)&bro,  g_bro);
    cudaGetSymbolAddress((void**)&cd,   g_cd);

    const int conv1_smem = (DN * 68 + 160 * 66) * (int)sizeof(float);
    cudaFuncSetAttribute(conv1_kernel, cudaFuncAttributeMaxDynamicSharedMemorySize,
                         conv1_smem);

    // x (B,T,D) -> bufA (B,D,T)
    transpose_kernel<<<dim3(TN / 32, DN / 32, BN), dim3(32, 8)>>>(x, bufA);

    struct Node { int node, depth, off; };
    const Node nodes[7] = {{0,0,0},{1,1,0},{2,2,0},{3,2,2},{4,1,1},{5,2,1},{6,2,3}};

    for (int ni = 0; ni < 7; ni++) {
        int node = nodes[ni].node, depth = nodes[ni].depth, off = nodes[ni].off;
        int s = 1 << depth;
        int L = 512 >> depth;
        int hLen = L + 2;
        int strideB = 2 * s;
        float* Min  = (depth & 1) ? bufB : bufA;
        float* Mout = (depth & 1) ? bufA : bufB;
        long long CL = (long long)BN * DN * L;
        int N = BN * DN * L;

        dim3 g1((hLen + LT - 1) / LT, CHN / 64, 64);
        dim3 g2((L + LT - 1) / LT, DN / 64, 64);

        // phi (even) / psi (odd)
        conv1_kernel<<<g1, 256, conv1_smem>>>(Min, TN, strideB,
                                              (long long)off, (long long)(off + s),
                                              L, W1, b1, node * 4 + 0, hb);
        conv2_kernel<<<g2, 256>>>(hb, hLen, L, W2, b2, node * 4 + 0, bro);
        pw1_kernel<<<(N + 255) / 256, 256>>>(Min, TN, strideB,
                                             (long long)off, (long long)s, L, bro, cd);
        // eta (on d) / rho (on c)
        conv1_kernel<<<g1, 256, conv1_smem>>>(cd, L, 1, 0LL, CL,
                                              L, W1, b1, node * 4 + 2, hb);
        conv2_kernel<<<g2, 256>>>(hb, hLen, L, W2, b2, node * 4 + 2, bro);
        pw2_kernel<<<(N + 255) / 256, 256>>>(cd, L, bro, Mout, TN, strideB,
                                             (long long)off, (long long)s);
    }

    // residual add (reuse g_h as R) + projection
    addres_kernel<<<dim3(TN / 32, DN / 32, BN), dim3(32, 8)>>>(x, bufB, hb);
    proj_kernel<<<dim3(DN / 64, OUTL / 64, BN), 256>>>(hb, Wp, out);
}

// round 7
// speedup vs baseline: 1.0479x; 1.0479x over previous
#include <cuda_runtime.h>
#include <cuda_bf16.h>

// SCINet on GB300 — round 7: tf32 tensor-core convs (mma.sync.m16n8k8),
// fp32 accumulate. im2col resolved at fragment-load time from the x smem tile.
// Everything else (tree addressing, pointwise, proj) unchanged fp32.
// Byte-identical resubmit of R6 after full fragment-layout audit (no bugs found).

#define BN   32
#define DN   192
#define CHN  768
#define TN   1024
#define OUTL 512

// ---------------- helpers ----------------------------------------------------
__device__ __forceinline__ unsigned tf32r(float x) {
    unsigned r;
    asm("cvt.rna.tf32.f32 %0, %1;" : "=r"(r) : "f"(x));
    return r;
}
__device__ __forceinline__ void mma_tf32(float& c0, float& c1, float& c2, float& c3,
                                         unsigned a0, unsigned a1, unsigned a2, unsigned a3,
                                         unsigned b0, unsigned b1) {
    asm("mma.sync.aligned.m16n8k8.row.col.f32.tf32.tf32.f32 "
        "{%0,%1,%2,%3},{%4,%5,%6,%7},{%8,%9},{%0,%1,%2,%3};"
        : "+f"(c0), "+f"(c1), "+f"(c2), "+f"(c3)
        : "r"(a0), "r"(a1), "r"(a2), "r"(a3), "r"(b0), "r"(b1));
}
__device__ __forceinline__ unsigned ldsu(const float* p) {
    return __float_as_uint(*p);
}
__device__ __forceinline__ unsigned long long pk2(float lo, float hi) {
    unsigned long long r;
    asm("mov.b64 %0, {%1, %2};" : "=l"(r) : "f"(lo), "f"(hi));
    return r;
}
__device__ __forceinline__ void upk2(float& lo, float& hi, unsigned long long v) {
    asm("mov.b64 {%0, %1}, %2;" : "=f"(lo), "=f"(hi) : "l"(v));
}
__device__ __forceinline__ void fma2(unsigned long long& d,
                                     unsigned long long a, unsigned long long b) {
    asm("fma.rn.f32x2 %0, %1, %2, %0;" : "+l"(d) : "l"(a), "l"(b));
}

// ---------------- static device scratch -------------------------------------
__device__ float g_bufA[BN * DN * TN];
__device__ float g_bufB[BN * DN * TN];
__device__ float g_h  [2 * BN * CHN * 514];
__device__ float g_bro[2 * BN * DN * 512];
__device__ float g_cd [2 * BN * DN * 512];

// ---------------- transpose x (B,T,D) -> (B,D,T) ----------------------------
__global__ void transpose_kernel(const float* __restrict__ x, float* __restrict__ o) {
    __shared__ float tile[32][33];
    int b = blockIdx.z, t0 = blockIdx.x * 32, d0 = blockIdx.y * 32;
    int tx = threadIdx.x, ty = threadIdx.y;
    for (int i = ty; i < 32; i += 8)
        tile[i][tx] = x[((size_t)b * TN + t0 + i) * DN + d0 + tx];
    __syncthreads();
    for (int i = ty; i < 32; i += 8)
        o[((size_t)b * DN + d0 + i) * TN + t0 + tx] = tile[tx][i];
}

__global__ void addres_kernel(const float* __restrict__ x, const float* __restrict__ tr,
                              float* __restrict__ R) {
    __shared__ float tile[32][33];
    int b = blockIdx.z, t0 = blockIdx.x * 32, d0 = blockIdx.y * 32;
    int tx = threadIdx.x, ty = threadIdx.y;
    for (int i = ty; i < 32; i += 8)
        tile[i][tx] = x[((size_t)b * TN + t0 + i) * DN + d0 + tx];
    __syncthreads();
    for (int i = ty; i < 32; i += 8) {
        size_t oo = ((size_t)b * DN + d0 + i) * TN + t0 + tx;
        R[oo] = tile[tx][i] + tr[oo];
    }
}

// ---------------- conv1: Cin=192 -> Cout=768, k=5, repl-pad, LeakyReLU, tf32 MMA
// CTA tile: 64co x 64l. Warps 8: warp_co = wid&3 (16co), warp_l = wid>>2 (32l).
// K = rest = ci*5+kk (960 total), processed in 6 chunks of 160 (32 ci).
__global__ void __launch_bounds__(256)
conv1_kernel(const float* __restrict__ in, int inRow, int inStride,
             long long goff0, long long goff1, int L,
             const float* __restrict__ W1, const float* __restrict__ b1,
             int wbase, float* __restrict__ h) {
    extern __shared__ float smem[];
    float* sx = smem;                 // [192][68]  (tf32-rounded x, cols l0-3 .. l0+64)
    float* sw = smem + DN * 68;       // [160][72]  (tf32-rounded weights, rest x co)

    int z = blockIdx.z;               // g*32+b
    int g = z >> 5, b = z & 31;
    int l0 = blockIdx.x * 64;
    int co0 = blockIdx.y * 64;
    int hLen = L + 2;
    int branch = wbase + g;
    long long goff = g ? goff1 : goff0;
    int tid = threadIdx.x;

    const float* inB = in + goff + (size_t)b * DN * inRow;

    for (int idx = tid; idx < DN * 68; idx += 256) {
        int ci = idx / 68;
        int col = idx - ci * 68;
        int t = l0 + col - 3;
        t = max(0, min(L - 1, t));
        sx[idx] = __uint_as_float(tf32r(inB[(size_t)ci * inRow + (size_t)t * inStride]));
    }

    int lane = tid & 31, wid = tid >> 5;
    int warp_co = wid & 3, warp_l = wid >> 2;
    int g4 = lane >> 2, tig = lane & 3;
    const float* Wb = W1 + (size_t)branch * CHN * DN * 5;

    float c[4][4];
#pragma unroll
    for (int a = 0; a < 4; a++)
#pragma unroll
        for (int i = 0; i < 4; i++) c[a][i] = 0.f;

    for (int cc = 0; cc < DN; cc += 32) {
        __syncthreads();
        for (int idx = tid; idx < 64 * 160; idx += 256) {
            int co = idx / 160;
            int rest = idx - co * 160;
            sw[rest * 72 + co] = __uint_as_float(
                tf32r(Wb[(size_t)(co0 + co) * (DN * 5) + (size_t)cc * 5 + rest]));
        }
        __syncthreads();
#pragma unroll 4
        for (int slab = 0; slab < 20; ++slab) {
            int rb = slab * 8;
            // A fragment: rows = warp_co*16 + g4 (+8), cols = tig (+4)
            const float* ap = sw + warp_co * 16 + g4;
            unsigned A0 = ldsu(ap + (rb + tig) * 72);
            unsigned A1 = ldsu(ap + (rb + tig) * 72 + 8);
            unsigned A2 = ldsu(ap + (rb + tig + 4) * 72);
            unsigned A3 = ldsu(ap + (rb + tig + 4) * 72 + 8);
            // B fragment rows: rest = rb+tig, rb+tig+4 -> (ci, kk)
            int r0 = rb + tig, r1 = r0 + 4;
            int ci0 = r0 / 5, k0 = r0 - ci0 * 5;
            int ci1 = r1 / 5, k1 = r1 - ci1 * 5;
            const float* b0p = sx + (cc + ci0) * 68 + warp_l * 32 + k0 + g4;
            const float* b1p = sx + (cc + ci1) * 68 + warp_l * 32 + k1 + g4;
#pragma unroll
            for (int a = 0; a < 4; a++) {
                unsigned B0 = ldsu(b0p + a * 8);
                unsigned B1 = ldsu(b1p + a * 8);
                mma_tf32(c[a][0], c[a][1], c[a][2], c[a][3], A0, A1, A2, A3, B0, B1);
            }
        }
    }

    // epilogue: bias + LeakyReLU; rows co_t, co_t+8; cols pairs (tig*2, +1)
    {
        int co_t = co0 + warp_co * 16 + g4;
        float bias_lo = b1[branch * CHN + co_t];
        float bias_hi = b1[branch * CHN + co_t + 8];
        float* hp0 = h + ((size_t)z * CHN + co_t) * hLen;
        float* hp1 = hp0 + (size_t)8 * hLen;
#pragma unroll
        for (int a = 0; a < 4; a++) {
            int l = l0 + warp_l * 32 + a * 8 + tig * 2;
            if (l < hLen) {
                float v0 = c[a][0] + bias_lo, v1 = c[a][1] + bias_lo;
                float v2 = c[a][2] + bias_hi, v3 = c[a][3] + bias_hi;
                v0 = v0 > 0.f ? v0 : 0.01f * v0;
                v1 = v1 > 0.f ? v1 : 0.01f * v1;
                v2 = v2 > 0.f ? v2 : 0.01f * v2;
                v3 = v3 > 0.f ? v3 : 0.01f * v3;
                *(float2*)(hp0 + l) = make_float2(v0, v1);
                *(float2*)(hp1 + l) = make_float2(v2, v3);
            }
        }
    }
}

// ---------------- conv2: Cin=768 -> Cout=192, k=3, valid, Tanh, tf32 MMA ------
// CTA tile 64co x 64l; K = rest = ch*3+kk (2304), chunks of 96 (32 ch).
__global__ void __launch_bounds__(256)
conv2_kernel(const float* __restrict__ h, int hLen, int L,
             const float* __restrict__ W2, const float* __restrict__ b2,
             int wbase, float* __restrict__ bro) {
    __shared__ float sh[32 * 68];     // tf32-rounded h chunk, cols l0 .. l0+65
    __shared__ float sw[96 * 72];     // tf32-rounded weights

    int z = blockIdx.z;
    int g = z >> 5;
    int l0 = blockIdx.x * 64;
    int co0 = blockIdx.y * 64;
    int branch = wbase + g;
    int tid = threadIdx.x;

    const float* hB = h + (size_t)z * CHN * hLen;
    const float* Wb = W2 + (size_t)branch * DN * CHN * 3;

    int lane = tid & 31, wid = tid >> 5;
    int warp_co = wid & 3, warp_l = wid >> 2;
    int g4 = lane >> 2, tig = lane & 3;

    float c[4][4];
#pragma unroll
    for (int a = 0; a < 4; a++)
#pragma unroll
        for (int i = 0; i < 4; i++) c[a][i] = 0.f;

    for (int chc = 0; chc < CHN; chc += 32) {
        __syncthreads();
        for (int idx = tid; idx < 32 * 68; idx += 256) {
            int r = idx / 68;
            int cpos = idx - r * 68;
            int l = min(l0 + cpos, hLen - 1);
            sh[idx] = __uint_as_float(tf32r(hB[(size_t)(chc + r) * hLen + l]));
        }
        for (int idx = tid; idx < 64 * 96; idx += 256) {
            int co = idx / 96;
            int rest = idx - co * 96;
            sw[rest * 72 + co] = __uint_as_float(
                tf32r(Wb[(size_t)(co0 + co) * (CHN * 3) + (size_t)chc * 3 + rest]));
        }
        __syncthreads();
#pragma unroll 4
        for (int slab = 0; slab < 12; ++slab) {
            int rb = slab * 8;
            const float* ap = sw + warp_co * 16 + g4;
            unsigned A0 = ldsu(ap + (rb + tig) * 72);
            unsigned A1 = ldsu(ap + (rb + tig) * 72 + 8);
            unsigned A2 = ldsu(ap + (rb + tig + 4) * 72);
            unsigned A3 = ldsu(ap + (rb + tig + 4) * 72 + 8);
            int r0 = rb + tig, r1 = r0 + 4;
            int ch0 = r0 / 3, k0 = r0 - ch0 * 3;
            int ch1 = r1 / 3, k1 = r1 - ch1 * 3;
            const float* b0p = sh + ch0 * 68 + warp_l * 32 + k0 + g4;
            const float* b1p = sh + ch1 * 68 + warp_l * 32 + k1 + g4;
#pragma unroll
            for (int a = 0; a < 4; a++) {
                unsigned B0 = ldsu(b0p + a * 8);
                unsigned B1 = ldsu(b1p + a * 8);
                mma_tf32(c[a][0], c[a][1], c[a][2], c[a][3], A0, A1, A2, A3, B0, B1);
            }
        }
    }

    {
        int co_t = co0 + warp_co * 16 + g4;
        float bias_lo = b2[branch * DN + co_t];
        float bias_hi = b2[branch * DN + co_t + 8];
        float* op0 = bro + ((size_t)z * DN + co_t) * L;
        float* op1 = op0 + (size_t)8 * L;
#pragma unroll
        for (int a = 0; a < 4; a++) {
            int l = l0 + warp_l * 32 + a * 8 + tig * 2;
            if (l < L) {
                *(float2*)(op0 + l) = make_float2(tanhf(c[a][0] + bias_lo),
                                                  tanhf(c[a][1] + bias_lo));
                *(float2*)(op1 + l) = make_float2(tanhf(c[a][2] + bias_hi),
                                                  tanhf(c[a][3] + bias_hi));
            }
        }
    }
}

// ---------------- pointwise --------------------------------------------------
__global__ void pw1_kernel(const float* __restrict__ M, int mRow, int strideB,
                           long long off, long long sHalf, int L,
                           const float* __restrict__ bro, float* __restrict__ cd) {
    int i = blockIdx.x * 256 + threadIdx.x;
    int N = BN * DN * L;
    if (i >= N) return;
    int t = i % L;
    int bd = i / L;
    size_t pos = (size_t)bd * mRow + (size_t)t * strideB + off;
    float ev = M[pos];
    float od = M[pos + sHalf];
    size_t CL = (size_t)N;
    cd[i]      = od * expf(bro[i]);        // d = odd * exp(phi)
    cd[CL + i] = ev * expf(bro[CL + i]);   // c = even * exp(psi)
}

__global__ void pw2_kernel(const float* __restrict__ cd, int L,
                           const float* __restrict__ bro, float* __restrict__ M,
                           int mRow, int strideB, long long off, long long sHalf) {
    int i = blockIdx.x * 256 + threadIdx.x;
    int N = BN * DN * L;
    if (i >= N) return;
    int t = i % L;
    int bd = i / L;
    size_t CL = (size_t)N;
    float dv = cd[i];
    float cv = cd[CL + i];
    size_t pos = (size_t)bd * mRow + (size_t)t * strideB + off;
    M[pos]         = cv + bro[i];          // even_up = c + eta(d)
    M[pos + sHalf] = dv - bro[CL + i];     // odd_up  = d - rho(c)
}

// ---------------- projection (fp32, unchanged) -------------------------------
__global__ void __launch_bounds__(256)
proj_kernel(const float* __restrict__ R, const float* __restrict__ Wp,
            float* __restrict__ out) {
    __shared__ float sW[32 * 66];
    __shared__ float sR[32 * 68];
    int d0 = blockIdx.x * 64;
    int o0 = blockIdx.y * 64;
    int b = blockIdx.z;
    int tid = threadIdx.x;
    int og = tid >> 3, dg = tid & 7;
    unsigned long long acc2[8];
#pragma unroll
    for (int i = 0; i < 8; i++) acc2[i] = 0ULL;
    for (int t0 = 0; t0 < TN; t0 += 32) {
        __syncthreads();
        for (int idx = tid; idx < 2048; idx += 256) {
            int t = idx & 31, o = idx >> 5;
            sW[t * 66 + o] = Wp[(size_t)(o0 + o) * TN + t0 + t];
        }
        for (int idx = tid; idx < 2048; idx += 256) {
            int t = idx & 31, d = idx >> 5;
            sR[t * 68 + d] = R[((size_t)b * DN + d0 + d) * TN + t0 + t];
        }
        __syncthreads();
        for (int t = 0; t < 32; t++) {
            const float* rp = &sR[t * 68 + dg * 8];
            float4 r0 = *(const float4*)(rp);
            float4 r1 = *(const float4*)(rp + 4);
            unsigned long long rd[8];
            rd[0] = pk2(r0.x, r0.x); rd[1] = pk2(r0.y, r0.y);
            rd[2] = pk2(r0.z, r0.z); rd[3] = pk2(r0.w, r0.w);
            rd[4] = pk2(r1.x, r1.x); rd[5] = pk2(r1.y, r1.y);
            rd[6] = pk2(r1.z, r1.z); rd[7] = pk2(r1.w, r1.w);
            unsigned long long w2 =
                *(const unsigned long long*)&sW[t * 66 + og * 2];
#pragma unroll
            for (int i = 0; i < 8; i++) fma2(acc2[i], w2, rd[i]);
        }
    }
    {
        int o = o0 + og * 2;
        float* out0 = out + ((size_t)b * OUTL + o) * DN + d0 + dg * 8;
        float* out1 = out0 + DN;
#pragma unroll
        for (int i = 0; i < 8; i++) {
            float v0, v1;
            upk2(v0, v1, acc2[i]);
            out0[i] = v0;
            out1[i] = v1;
        }
    }
}

// ---------------- host -------------------------------------------------------
extern "C" void kernel_launch(void* const* d_in, const int* in_sizes, int n_in,
                              void* d_out, int out_size) {
    const float* x  = (const float*)d_in[0];
    const float* W1 = (const float*)d_in[1];
    const float* b1 = (const float*)d_in[2];
    const float* W2 = (const float*)d_in[3];
    const float* b2 = (const float*)d_in[4];
    const float* Wp = (const float*)d_in[5];
    float* out = (float*)d_out;

    float *bufA, *bufB, *hb, *bro, *cd;
    cudaGetSymbolAddress((void**)&bufA, g_bufA);
    cudaGetSymbolAddress((void**)&bufB, g_bufB);
    cudaGetSymbolAddress((void**)&hb,   g_h);
    cudaGetSymbolAddress((void**)&bro,  g_bro);
    cudaGetSymbolAddress((void**)&cd,   g_cd);

    const int conv1_smem = (DN * 68 + 160 * 72) * (int)sizeof(float);   // 96 KB
    cudaFuncSetAttribute(conv1_kernel, cudaFuncAttributeMaxDynamicSharedMemorySize,
                         conv1_smem);

    transpose_kernel<<<dim3(TN / 32, DN / 32, BN), dim3(32, 8)>>>(x, bufA);

    struct Node { int node, depth, off; };
    const Node nodes[7] = {{0,0,0},{1,1,0},{2,2,0},{3,2,2},{4,1,1},{5,2,1},{6,2,3}};

    for (int ni = 0; ni < 7; ni++) {
        int node = nodes[ni].node, depth = nodes[ni].depth, off = nodes[ni].off;
        int s = 1 << depth;
        int L = 512 >> depth;
        int hLen = L + 2;
        int strideB = 2 * s;
        float* Min  = (depth & 1) ? bufB : bufA;
        float* Mout = (depth & 1) ? bufA : bufB;
        long long CL = (long long)BN * DN * L;
        int N = BN * DN * L;

        dim3 g1((hLen + 63) / 64, CHN / 64, 64);
        dim3 g2(L / 64, DN / 64, 64);

        conv1_kernel<<<g1, 256, conv1_smem>>>(Min, TN, strideB,
                                              (long long)off, (long long)(off + s),
                                              L, W1, b1, node * 4 + 0, hb);
        conv2_kernel<<<g2, 256>>>(hb, hLen, L, W2, b2, node * 4 + 0, bro);
        pw1_kernel<<<(N + 255) / 256, 256>>>(Min, TN, strideB,
                                             (long long)off, (long long)s, L, bro, cd);
        conv1_kernel<<<g1, 256, conv1_smem>>>(cd, L, 1, 0LL, CL,
                                              L, W1, b1, node * 4 + 2, hb);
        conv2_kernel<<<g2, 256>>>(hb, hLen, L, W2, b2, node * 4 + 2, bro);
        pw2_kernel<<<(N + 255) / 256, 256>>>(cd, L, bro, Mout, TN, strideB,
                                             (long long)off, (long long)s);
    }

    addres_kernel<<<dim3(TN / 32, DN / 32, BN), dim3(32, 8)>>>(x, bufB, hb);
    proj_kernel<<<dim3(DN / 64, OUTL / 64, BN), 256>>>(hb, Wp, out);
}

// round 13
// speedup vs baseline: 1.1463x; 1.0939x over previous
#include <cuda_runtime.h>
#include <cuda_bf16.h>
#include <cstdint>

// SCINet on GB300 — round 13: hybrid dual-pipe convs (audited resubmit, 5th).
// Warps 0-3: tf32 mma.sync (tensor pipe), warps 4-7: scalar FFMA (fma pipe),
// disjoint co ranges, shared x tile, cp.async double-buffered weight chunks.
// Rationale: measured R5 (fp32) == R7 (tf32 mma) == ~17ms => legacy HMMA on
// sm_103 is FFMA-class; running both pipes concurrently ~doubles throughput.

#define BN   32
#define DN   192
#define CHN  768
#define TN   1024
#define OUTL 512

// ---------------- helpers ----------------------------------------------------
__device__ __forceinline__ unsigned ldsu(const float* p) { return __float_as_uint(*p); }

__device__ __forceinline__ void mma_tf32(float& c0, float& c1, float& c2, float& c3,
                                         unsigned a0, unsigned a1, unsigned a2, unsigned a3,
                                         unsigned b0, unsigned b1) {
    asm("mma.sync.aligned.m16n8k8.row.col.f32.tf32.tf32.f32 "
        "{%0,%1,%2,%3},{%4,%5,%6,%7},{%8,%9},{%0,%1,%2,%3};"
        : "+f"(c0), "+f"(c1), "+f"(c2), "+f"(c3)
        : "r"(a0), "r"(a1), "r"(a2), "r"(a3), "r"(b0), "r"(b1));
}
__device__ __forceinline__ void cp16(float* dst, const float* src) {
    asm volatile("cp.async.ca.shared.global [%0], [%1], 16;"
                 :: "r"((uint32_t)__cvta_generic_to_shared(dst)), "l"(src) : "memory");
}
__device__ __forceinline__ void cp8(float* dst, const float* src) {
    asm volatile("cp.async.ca.shared.global [%0], [%1], 8;"
                 :: "r"((uint32_t)__cvta_generic_to_shared(dst)), "l"(src) : "memory");
}
#define CP_COMMIT() asm volatile("cp.async.commit_group;" ::: "memory")
#define CP_WAIT1()  asm volatile("cp.async.wait_group 1;" ::: "memory")
#define CP_WAIT0()  asm volatile("cp.async.wait_group 0;" ::: "memory")

__device__ __forceinline__ unsigned long long pk2(float lo, float hi) {
    unsigned long long r;
    asm("mov.b64 %0, {%1, %2};" : "=l"(r) : "f"(lo), "f"(hi));
    return r;
}
__device__ __forceinline__ void upk2(float& lo, float& hi, unsigned long long v) {
    asm("mov.b64 {%0, %1}, %2;" : "=f"(lo), "=f"(hi) : "l"(v));
}
__device__ __forceinline__ void fma2(unsigned long long& d,
                                     unsigned long long a, unsigned long long b) {
    asm("fma.rn.f32x2 %0, %1, %2, %0;" : "+l"(d) : "l"(a), "l"(b));
}

// ---------------- static device scratch --------------------------------------
__device__ float g_bufA[BN * DN * TN];
__device__ float g_bufB[BN * DN * TN];
__device__ float g_h  [2 * BN * CHN * 514];
__device__ float g_bro[2 * BN * DN * 512];
__device__ float g_cd [2 * BN * DN * 512];

// ---------------- transpose / residual ---------------------------------------
__global__ void transpose_kernel(const float* __restrict__ x, float* __restrict__ o) {
    __shared__ float tile[32][33];
    int b = blockIdx.z, t0 = blockIdx.x * 32, d0 = blockIdx.y * 32;
    int tx = threadIdx.x, ty = threadIdx.y;
    for (int i = ty; i < 32; i += 8)
        tile[i][tx] = x[((size_t)b * TN + t0 + i) * DN + d0 + tx];
    __syncthreads();
    for (int i = ty; i < 32; i += 8)
        o[((size_t)b * DN + d0 + i) * TN + t0 + tx] = tile[tx][i];
}

__global__ void addres_kernel(const float* __restrict__ x, const float* __restrict__ tr,
                              float* __restrict__ R) {
    __shared__ float tile[32][33];
    int b = blockIdx.z, t0 = blockIdx.x * 32, d0 = blockIdx.y * 32;
    int tx = threadIdx.x, ty = threadIdx.y;
    for (int i = ty; i < 32; i += 8)
        tile[i][tx] = x[((size_t)b * TN + t0 + i) * DN + d0 + tx];
    __syncthreads();
    for (int i = ty; i < 32; i += 8) {
        size_t oo = ((size_t)b * DN + d0 + i) * TN + t0 + tx;
        R[oo] = tile[tx][i] + tr[oo];
    }
}

// ---------------- conv1 hybrid: 192->768, k=5, repl-pad, LeakyReLU ------------
// CTA 128co x 64l. Warps 0-3 MMA (co 0..63), warps 4-7 FFMA (co 64..127).
// K = rest = ci*5+kk (960), chunks of 32, cp.async double-buffered weights.
__global__ void __launch_bounds__(256)
conv1_hyb(const float* __restrict__ in, int inRow, int inStride,
          long long goff0, long long goff1, int L,
          const float* __restrict__ W1, const float* __restrict__ b1,
          int wbase, float* __restrict__ h) {
    extern __shared__ float smem[];
    float* sx  = smem;               // [192][68] raw f32
    float* swb[2] = { smem + 192 * 68, smem + 192 * 68 + 128 * 36 };  // [128][36]

    int hLen = L + 2;
    int tid = threadIdx.x, lane = tid & 31, wid = tid >> 5;
    int z = blockIdx.z, g = z >> 5, b = z & 31;
    int l0 = blockIdx.x * 64;
    int co0 = blockIdx.y * 128;
    int branch = wbase + g;
    const float* inB = in + (g ? goff1 : goff0) + (size_t)b * DN * inRow;
    const float* Wb = W1 + (size_t)branch * CHN * 960 + (size_t)co0 * 960;

    // x tile (once): clamped time index = replication pad
    for (int idx = tid; idx < 192 * 68; idx += 256) {
        int ci = idx / 68, col = idx - ci * 68;
        int t = l0 + col - 3;
        t = max(0, min(L - 1, t));
        sx[idx] = inB[(size_t)ci * inRow + (size_t)t * inStride];
    }
    // prefetch weight chunk 0
    for (int i = tid; i < 1024; i += 256) {
        int co = i >> 3, s = i & 7;
        cp16(swb[0] + co * 36 + s * 4, Wb + (size_t)co * 960 + s * 4);
    }
    CP_COMMIT();

    int g4 = lane >> 2, tig = lane & 3;       // MMA lane ids
    int co_gF = lane >> 3, l_gF = lane & 7;   // FFMA lane ids
    float acc[32];
#pragma unroll
    for (int i = 0; i < 32; i++) acc[i] = 0.f;

    for (int ch = 0; ch < 30; ++ch) {
        float* cur = swb[ch & 1];
        if (ch + 1 < 30) {
            float* nxt = swb[(ch + 1) & 1];
            int rb2 = (ch + 1) * 32;
            for (int i = tid; i < 1024; i += 256) {
                int co = i >> 3, s = i & 7;
                cp16(nxt + co * 36 + s * 4, Wb + (size_t)co * 960 + rb2 + s * 4);
            }
            CP_COMMIT();
            CP_WAIT1();
        } else {
            CP_WAIT0();
        }
        __syncthreads();
        int rbase = ch * 32;
        if (wid < 4) {
            // tensor pipe: warp tile 16co x 64l (8 n-atoms)
            const float* ap = cur + (wid * 16 + g4) * 36;
#pragma unroll
            for (int slab = 0; slab < 4; ++slab) {
                int rb = slab * 8;
                unsigned A0 = ldsu(ap + rb + tig);
                unsigned A1 = ldsu(ap + 8 * 36 + rb + tig);
                unsigned A2 = ldsu(ap + rb + tig + 4);
                unsigned A3 = ldsu(ap + 8 * 36 + rb + tig + 4);
                int r0 = rbase + rb + tig, r1 = r0 + 4;
                int ci0 = r0 / 5, k0 = r0 - ci0 * 5;
                int ci1 = r1 / 5, k1 = r1 - ci1 * 5;
                const float* b0p = sx + ci0 * 68 + k0 + g4;
                const float* b1p = sx + ci1 * 68 + k1 + g4;
#pragma unroll
                for (int a = 0; a < 8; ++a) {
                    unsigned B0 = ldsu(b0p + a * 8);
                    unsigned B1 = ldsu(b1p + a * 8);
                    mma_tf32(acc[a * 4], acc[a * 4 + 1], acc[a * 4 + 2], acc[a * 4 + 3],
                             A0, A1, A2, A3, B0, B1);
                }
            }
        } else {
            // fma pipe: warp tile 16co x 64l, thread 4co x 8l
            const float* wp = cur + (64 + (wid - 4) * 16 + co_gF * 4) * 36;
#pragma unroll 4
            for (int r = 0; r < 32; ++r) {
                int rg = rbase + r;
                int ci = rg / 5, kk = rg - ci * 5;
                const float* xp = sx + ci * 68 + l_gF * 8 + kk;
                float x0 = xp[0], x1 = xp[1], x2 = xp[2], x3 = xp[3];
                float x4 = xp[4], x5 = xp[5], x6 = xp[6], x7 = xp[7];
#pragma unroll
                for (int j = 0; j < 4; ++j) {
                    float w = wp[j * 36 + r];
                    float* a = acc + j * 8;
                    a[0] = fmaf(w, x0, a[0]); a[1] = fmaf(w, x1, a[1]);
                    a[2] = fmaf(w, x2, a[2]); a[3] = fmaf(w, x3, a[3]);
                    a[4] = fmaf(w, x4, a[4]); a[5] = fmaf(w, x5, a[5]);
                    a[6] = fmaf(w, x6, a[6]); a[7] = fmaf(w, x7, a[7]);
                }
            }
        }
        __syncthreads();
    }

    if (wid < 4) {
        int co_t = co0 + wid * 16 + g4;
        float bias_lo = b1[branch * CHN + co_t];
        float bias_hi = b1[branch * CHN + co_t + 8];
        float* hp0 = h + ((size_t)z * CHN + co_t) * hLen;
        float* hp1 = hp0 + (size_t)8 * hLen;
#pragma unroll
        for (int a = 0; a < 8; ++a) {
            int l = l0 + a * 8 + tig * 2;
            if (l < hLen) {
                float v0 = acc[a * 4] + bias_lo, v1 = acc[a * 4 + 1] + bias_lo;
                float v2 = acc[a * 4 + 2] + bias_hi, v3 = acc[a * 4 + 3] + bias_hi;
                v0 = v0 > 0.f ? v0 : 0.01f * v0;
                v1 = v1 > 0.f ? v1 : 0.01f * v1;
                v2 = v2 > 0.f ? v2 : 0.01f * v2;
                v3 = v3 > 0.f ? v3 : 0.01f * v3;
                *(float2*)(hp0 + l) = make_float2(v0, v1);
                *(float2*)(hp1 + l) = make_float2(v2, v3);
            }
        }
    } else {
#pragma unroll
        for (int j = 0; j < 4; ++j) {
            int co_t = co0 + 64 + (wid - 4) * 16 + co_gF * 4 + j;
            float bias = b1[branch * CHN + co_t];
            float* hp = h + ((size_t)z * CHN + co_t) * hLen;
#pragma unroll
            for (int i = 0; i < 8; ++i) {
                int l = l0 + l_gF * 8 + i;
                if (l < hLen) {
                    float v = acc[j * 8 + i] + bias;
                    hp[l] = v > 0.f ? v : 0.01f * v;
                }
            }
        }
    }
}

// ---------------- conv2 hybrid: 768->192, k=3, valid, Tanh --------------------
// CTA 96co x 64l. Warps 0-3 MMA (co 0..63), warps 4-7 FFMA (co 64..95).
// K = rest = ch*3+kk (2304), chunks of 48 (16 ch), cp.async both tiles.
__global__ void __launch_bounds__(256)
conv2_hyb(const float* __restrict__ h, int hLen,
          const float* __restrict__ W2, const float* __restrict__ b2,
          int wbase, float* __restrict__ bro, int L) {
    extern __shared__ float smem[];
    float* shb[2] = { smem, smem + 16 * 68 };                       // [16][68]
    float* swb[2] = { smem + 2 * 16 * 68, smem + 2 * 16 * 68 + 96 * 52 };  // [96][52]

    int tid = threadIdx.x, lane = tid & 31, wid = tid >> 5;
    int z = blockIdx.z, g = z >> 5;
    int l0 = blockIdx.x * 64;
    int co0 = blockIdx.y * 96;
    int branch = wbase + g;
    const float* hB = h + (size_t)z * CHN * hLen;
    const float* Wb = W2 + (size_t)branch * DN * 2304 + (size_t)co0 * 2304;

    // prefetch chunk 0: h rows 0..15 (66 cols) + weights 96co x 48rest
    for (int i = tid; i < 528; i += 256) {
        int r = i / 33, s = i - r * 33;
        cp8(shb[0] + r * 68 + s * 2, hB + (size_t)r * hLen + l0 + s * 2);
    }
    for (int i = tid; i < 1152; i += 256) {
        int co = i / 12, s = i - co * 12;
        cp16(swb[0] + co * 52 + s * 4, Wb + (size_t)co * 2304 + s * 4);
    }
    CP_COMMIT();

    int g4 = lane >> 2, tig = lane & 3;
    int co_gF = lane >> 3, l_gF = lane & 7;
    float acc[32];
#pragma unroll
    for (int i = 0; i < 32; i++) acc[i] = 0.f;

    for (int ch = 0; ch < 48; ++ch) {
        float* shc = shb[ch & 1];
        float* swc = swb[ch & 1];
        if (ch + 1 < 48) {
            float* shn = shb[(ch + 1) & 1];
            float* swn = swb[(ch + 1) & 1];
            int row2 = (ch + 1) * 16, rb2 = (ch + 1) * 48;
            for (int i = tid; i < 528; i += 256) {
                int r = i / 33, s = i - r * 33;
                cp8(shn + r * 68 + s * 2, hB + (size_t)(row2 + r) * hLen + l0 + s * 2);
            }
            for (int i = tid; i < 1152; i += 256) {
                int co = i / 12, s = i - co * 12;
                cp16(swn + co * 52 + s * 4, Wb + (size_t)co * 2304 + rb2 + s * 4);
            }
            CP_COMMIT();
            CP_WAIT1();
        } else {
            CP_WAIT0();
        }
        __syncthreads();
        if (wid < 4) {
            const float* ap = swc + (wid * 16 + g4) * 52;
#pragma unroll
            for (int slab = 0; slab < 6; ++slab) {
                int rb = slab * 8;
                unsigned A0 = ldsu(ap + rb + tig);
                unsigned A1 = ldsu(ap + 8 * 52 + rb + tig);
                unsigned A2 = ldsu(ap + rb + tig + 4);
                unsigned A3 = ldsu(ap + 8 * 52 + rb + tig + 4);
                int r0 = rb + tig, r1 = r0 + 4;       // local rest (chunk mult of 3)
                int ci0 = r0 / 3, k0 = r0 - ci0 * 3;
                int ci1 = r1 / 3, k1 = r1 - ci1 * 3;
                const float* b0p = shc + ci0 * 68 + k0 + g4;
                const float* b1p = shc + ci1 * 68 + k1 + g4;
#pragma unroll
                for (int a = 0; a < 8; ++a) {
                    unsigned B0 = ldsu(b0p + a * 8);
                    unsigned B1 = ldsu(b1p + a * 8);
                    mma_tf32(acc[a * 4], acc[a * 4 + 1], acc[a * 4 + 2], acc[a * 4 + 3],
                             A0, A1, A2, A3, B0, B1);
                }
            }
        } else {
            const float* wp = swc + (64 + (wid - 4) * 8 + co_gF * 2) * 52;
#pragma unroll 6
            for (int r = 0; r < 48; ++r) {
                int ci = r / 3, kk = r - ci * 3;
                const float* xp = shc + ci * 68 + l_gF * 8 + kk;
                float x0 = xp[0], x1 = xp[1], x2 = xp[2], x3 = xp[3];
                float x4 = xp[4], x5 = xp[5], x6 = xp[6], x7 = xp[7];
#pragma unroll
                for (int j = 0; j < 2; ++j) {
                    float w = wp[j * 52 + r];
                    float* a = acc + j * 8;
                    a[0] = fmaf(w, x0, a[0]); a[1] = fmaf(w, x1, a[1]);
                    a[2] = fmaf(w, x2, a[2]); a[3] = fmaf(w, x3, a[3]);
                    a[4] = fmaf(w, x4, a[4]); a[5] = fmaf(w, x5, a[5]);
                    a[6] = fmaf(w, x6, a[6]); a[7] = fmaf(w, x7, a[7]);
                }
            }
        }
        __syncthreads();
    }

    if (wid < 4) {
        int co_t = co0 + wid * 16 + g4;
        float bias_lo = b2[branch * DN + co_t];
        float bias_hi = b2[branch * DN + co_t + 8];
        float* op0 = bro + ((size_t)z * DN + co_t) * L;
        float* op1 = op0 + (size_t)8 * L;
#pragma unroll
        for (int a = 0; a < 8; ++a) {
            int l = l0 + a * 8 + tig * 2;
            *(float2*)(op0 + l) = make_float2(tanhf(acc[a * 4] + bias_lo),
                                              tanhf(acc[a * 4 + 1] + bias_lo));
            *(float2*)(op1 + l) = make_float2(tanhf(acc[a * 4 + 2] + bias_hi),
                                              tanhf(acc[a * 4 + 3] + bias_hi));
        }
    } else {
#pragma unroll
        for (int j = 0; j < 2; ++j) {
            int co_t = co0 + 64 + (wid - 4) * 8 + co_gF * 2 + j;
            float bias = b2[branch * DN + co_t];
            float* op = bro + ((size_t)z * DN + co_t) * L;
#pragma unroll
            for (int i = 0; i < 8; ++i)
                op[l0 + l_gF * 8 + i] = tanhf(acc[j * 8 + i] + bias);
        }
    }
}

// ---------------- pointwise ---------------------------------------------------
__global__ void pw1_kernel(const float* __restrict__ M, int mRow, int strideB,
                           long long off, long long sHalf, int L,
                           const float* __restrict__ bro, float* __restrict__ cd) {
    int i = blockIdx.x * 256 + threadIdx.x;
    int N = BN * DN * L;
    if (i >= N) return;
    int t = i % L;
    int bd = i / L;
    size_t pos = (size_t)bd * mRow + (size_t)t * strideB + off;
    float ev = M[pos];
    float od = M[pos + sHalf];
    size_t CL = (size_t)N;
    cd[i]      = od * expf(bro[i]);        // d = odd * exp(phi)
    cd[CL + i] = ev * expf(bro[CL + i]);   // c = even * exp(psi)
}

__global__ void pw2_kernel(const float* __restrict__ cd, int L,
                           const float* __restrict__ bro, float* __restrict__ M,
                           int mRow, int strideB, long long off, long long sHalf) {
    int i = blockIdx.x * 256 + threadIdx.x;
    int N = BN * DN * L;
    if (i >= N) return;
    int t = i % L;
    int bd = i / L;
    size_t CL = (size_t)N;
    float dv = cd[i];
    float cv = cd[CL + i];
    size_t pos = (size_t)bd * mRow + (size_t)t * strideB + off;
    M[pos]         = cv + bro[i];          // even_up = c + eta(d)
    M[pos + sHalf] = dv - bro[CL + i];     // odd_up  = d - rho(c)
}

// ---------------- projection (fp32x2) -----------------------------------------
__global__ void __launch_bounds__(256)
proj_kernel(const float* __restrict__ R, const float* __restrict__ Wp,
            float* __restrict__ out) {
    __shared__ float sW[32 * 66];
    __shared__ float sR[32 * 68];
    int d0 = blockIdx.x * 64;
    int o0 = blockIdx.y * 64;
    int b = blockIdx.z;
    int tid = threadIdx.x;
    int og = tid >> 3, dg = tid & 7;
    unsigned long long acc2[8];
#pragma unroll
    for (int i = 0; i < 8; i++) acc2[i] = 0ULL;
    for (int t0 = 0; t0 < TN; t0 += 32) {
        __syncthreads();
        for (int idx = tid; idx < 2048; idx += 256) {
            int t = idx & 31, o = idx >> 5;
            sW[t * 66 + o] = Wp[(size_t)(o0 + o) * TN + t0 + t];
        }
        for (int idx = tid; idx < 2048; idx += 256) {
            int t = idx & 31, d = idx >> 5;
            sR[t * 68 + d] = R[((size_t)b * DN + d0 + d) * TN + t0 + t];
        }
        __syncthreads();
        for (int t = 0; t < 32; t++) {
            const float* rp = &sR[t * 68 + dg * 8];
            float4 r0 = *(const float4*)(rp);
            float4 r1 = *(const float4*)(rp + 4);
            unsigned long long rd[8];
            rd[0] = pk2(r0.x, r0.x); rd[1] = pk2(r0.y, r0.y);
            rd[2] = pk2(r0.z, r0.z); rd[3] = pk2(r0.w, r0.w);
            rd[4] = pk2(r1.x, r1.x); rd[5] = pk2(r1.y, r1.y);
            rd[6] = pk2(r1.z, r1.z); rd[7] = pk2(r1.w, r1.w);
            unsigned long long w2 =
                *(const unsigned long long*)&sW[t * 66 + og * 2];
#pragma unroll
            for (int i = 0; i < 8; i++) fma2(acc2[i], w2, rd[i]);
        }
    }
    {
        int o = o0 + og * 2;
        float* out0 = out + ((size_t)b * OUTL + o) * DN + d0 + dg * 8;
        float* out1 = out0 + DN;
#pragma unroll
        for (int i = 0; i < 8; i++) {
            float v0, v1;
            upk2(v0, v1, acc2[i]);
            out0[i] = v0;
            out1[i] = v1;
        }
    }
}

// ---------------- host --------------------------------------------------------
extern "C" void kernel_launch(void* const* d_in, const int* in_sizes, int n_in,
                              void* d_out, int out_size) {
    const float* x  = (const float*)d_in[0];
    const float* W1 = (const float*)d_in[1];
    const float* b1 = (const float*)d_in[2];
    const float* W2 = (const float*)d_in[3];
    const float* b2 = (const float*)d_in[4];
    const float* Wp = (const float*)d_in[5];
    float* out = (float*)d_out;

    float *bufA, *bufB, *hb, *bro, *cd;
    cudaGetSymbolAddress((void**)&bufA, g_bufA);
    cudaGetSymbolAddress((void**)&bufB, g_bufB);
    cudaGetSymbolAddress((void**)&hb,   g_h);
    cudaGetSymbolAddress((void**)&bro,  g_bro);
    cudaGetSymbolAddress((void**)&cd,   g_cd);

    const int conv1_smem = (192 * 68 + 2 * 128 * 36) * 4;   // 89088
    const int conv2_smem = (2 * 16 * 68 + 2 * 96 * 52) * 4; // 48640
    cudaFuncSetAttribute(conv1_hyb, cudaFuncAttributeMaxDynamicSharedMemorySize,
                         conv1_smem);
    cudaFuncSetAttribute(conv2_hyb, cudaFuncAttributeMaxDynamicSharedMemorySize,
                         conv2_smem);

    transpose_kernel<<<dim3(TN / 32, DN / 32, BN), dim3(32, 8)>>>(x, bufA);

    struct Node { int node, depth, off; };
    const Node nodes[7] = {{0,0,0},{1,1,0},{2,2,0},{3,2,2},{4,1,1},{5,2,1},{6,2,3}};

    for (int ni = 0; ni < 7; ni++) {
        int node = nodes[ni].node, depth = nodes[ni].depth, off = nodes[ni].off;
        int s = 1 << depth;
        int L = 512 >> depth;
        int hLen = L + 2;
        int strideB = 2 * s;
        float* Min  = (depth & 1) ? bufB : bufA;
        float* Mout = (depth & 1) ? bufA : bufB;
        long long CL = (long long)BN * DN * L;
        int N = BN * DN * L;

        dim3 g1((hLen + 63) / 64, CHN / 128, 64);
        dim3 g2(L / 64, DN / 96, 64);

        // phi (even) / psi (odd)
        conv1_hyb<<<g1, 256, conv1_smem>>>(Min, TN, strideB,
                                           (long long)off, (long long)(off + s),
                                           L, W1, b1, node * 4 + 0, hb);
        conv2_hyb<<<g2, 256, conv2_smem>>>(hb, hLen, W2, b2, node * 4 + 0, bro, L);
        pw1_kernel<<<(N + 255) / 256, 256>>>(Min, TN, strideB,
                                             (long long)off, (long long)s, L, bro, cd);
        // eta (on d) / rho (on c)
        conv1_hyb<<<g1, 256, conv1_smem>>>(cd, L, 1, 0LL, CL,
                                           L, W1, b1, node * 4 + 2, hb);
        conv2_hyb<<<g2, 256, conv2_smem>>>(hb, hLen, W2, b2, node * 4 + 2, bro, L);
        pw2_kernel<<<(N + 255) / 256, 256>>>(cd, L, bro, Mout, TN, strideB,
                                             (long long)off, (long long)s);
    }

    addres_kernel<<<dim3(TN / 32, DN / 32, BN), dim3(32, 8)>>>(x, bufB, hb);
    proj_kernel<<<dim3(DN / 64, OUTL / 64, BN), 256>>>(hb, Wp, out);
}